// round 9
// baseline (speedup 1.0000x reference)
#include <cuda_runtime.h>
#include <math.h>

// AnomalyAttention: B=2, L=2048, H=8, E=64, band |i-j| <= 63.
// out = concat( V [B,L,H,E] f32 , series [B,H,L,L] f32 ).
// RT=64 tiles, 512 threads, __launch_bounds__(512,2) -> 2 CTAs/SM (smem 108 KB).
// Series row = [0,jbase) zeros (bulk) | [jbase,jbase+160) direct STG | [jbase+160,2048) zeros (bulk),
// jbase per-warp, 16B aligned. Q in registers (shfl broadcast). Ps aliases Ks after GEMM1.

#define BN 2
#define HN 8
#define LN 2048
#define EN 64
#define RT 64          // rows per block
#define WROWS 192      // K window rows
#define KSTR 68        // K smem row stride (68%32=4 -> LDS.128 conflict-free)
#define VTSTR 196      // VT row stride (192 data + 4 zero pad; 49 mod 8 != 0 -> conflict-free)
#define PSSTR 160      // Ps row stride (broadcast reads; STS.32 lane-distinct conflict-free)
#define ZB_FLOATS 2048 // zero source (max segment 1980 floats)
#define SCALE_L2E 0.18033688011112042f   // 0.125 * log2(e)

typedef unsigned long long u64;

__device__ __forceinline__ u64 fma2(u64 a, u64 b, u64 c) {
    u64 d;
    asm("fma.rn.f32x2 %0, %1, %2, %3;" : "=l"(d) : "l"(a), "l"(b), "l"(c));
    return d;
}
__device__ __forceinline__ u64 pack2(float lo, float hi) {
    u64 d;
    asm("mov.b64 %0, {%1, %2};" : "=l"(d) : "f"(lo), "f"(hi));
    return d;
}
__device__ __forceinline__ float2 unpack2(u64 v) {
    float2 r;
    asm("mov.b64 {%0, %1}, %2;" : "=f"(r.x), "=f"(r.y) : "l"(v));
    return r;
}
__device__ __forceinline__ float ex2f(float x) {
    float y;
    asm("ex2.approx.ftz.f32 %0, %1;" : "=f"(y) : "f"(x));
    return y;
}
__device__ __forceinline__ unsigned smem_u32(const void* p) {
    return (unsigned)__cvta_generic_to_shared(p);
}
__device__ __forceinline__ void bulk_store(void* dst, unsigned src_smem, unsigned bytes) {
    asm volatile("cp.async.bulk.global.shared::cta.bulk_group [%0], [%1], %2;"
                 :: "l"(dst), "r"(src_smem), "r"(bytes) : "memory");
}

__global__ __launch_bounds__(512, 2)
void anomaly_attn_kernel(const float* __restrict__ Q,
                         const float* __restrict__ K,
                         const float* __restrict__ V,
                         float* __restrict__ out)
{
    extern __shared__ float sm[];
    float* Ks = sm;                        // WROWS * KSTR = 13056
    float* VT = Ks + WROWS * KSTR;         // EN * VTSTR   = 12544
    float* Zb = VT + EN * VTSTR;           // 2048
    float* Ps = Ks;                        // 64 * PSSTR = 10240, aliases Ks post-GEMM1

    const int bid = blockIdx.x;
    const int t   = bid & 31;
    const int h   = (bid >> 5) & 7;
    const int b   = bid >> 8;
    const int i0  = t * RT;
    const int wbase = min(max(i0 - 64, 0), LN - WROWS);

    const int tid  = threadIdx.x;
    const int lane = tid & 31;
    const int w    = tid >> 5;             // 16 warps x 4 rows
    const int ga   = 4 * w;
    const int gia  = i0 + ga;

    float* series = out + (size_t)BN * LN * HN * EN;
    const size_t growbase = (size_t)((b * HN + h) * LN);

    // ---- q -> registers (scaled); lane holds e = 2*lane, 2*lane+1 of 4 rows ----
    u64 q2[4];
#pragma unroll
    for (int r = 0; r < 4; r++) {
        const float2 qf = *(const float2*)&Q[(((size_t)b * LN + (gia + r)) * HN + h) * EN + 2 * lane];
        q2[r] = pack2(qf.x * SCALE_L2E, qf.y * SCALE_L2E);
    }

    // ---- cooperative fills ----
    {
        const int e4 = (tid & 15) * 4;
        const int r0 = tid >> 4;           // 0..31
#pragma unroll
        for (int r = r0; r < WROWS; r += 32)
            *(float4*)(Ks + r * KSTR + e4) =
                *(const float4*)&K[(((size_t)b * LN + (wbase + r)) * HN + h) * EN + e4];

        // VT[e][col]: coalesced LDG.32 gather, conflict-free STS.128
        const int e  = tid & 63;
        const int jg = (tid >> 6) * 4;     // 0..28
#pragma unroll
        for (int j4 = jg; j4 < WROWS; j4 += 32) {
            const float* vp = &V[(((size_t)b * LN + (wbase + j4)) * HN + h) * EN + e];
            float4 v;
            v.x = vp[0];
            v.y = vp[HN * EN];
            v.z = vp[2 * HN * EN];
            v.w = vp[3 * HN * EN];
            *(float4*)(VT + e * VTSTR + j4) = v;
        }
        *(float4*)(Zb + tid * 4) = make_float4(0.f, 0.f, 0.f, 0.f);   // 512*4 = 2048
        if (tid < EN)   // VT zero pad cols 192..195 (GEMM2 tail reads them)
            *(float4*)(VT + tid * VTSTR + WROWS) = make_float4(0.f, 0.f, 0.f, 0.f);
    }
    __syncthreads();

    // ---- per-warp geometry: aligned 160-col store window ----
    const int jbase = max(0, gia - 63) & ~3;            // 16B-aligned
    const int off   = jbase - wbase;                    // window col of jj=0, mult of 4
    const int spanw = min(LN - 1, gia + 66) - jbase;    // <= 133

    // ---- issue zero-segment bulk stores (overlap all compute) ----
    if (lane == 0) {
        asm volatile("fence.proxy.async.shared::cta;" ::: "memory");
        const unsigned zb_addr = smem_u32(Zb);
        const unsigned lbytes = (unsigned)jbase * 4u;
        const int rlen = LN - (jbase + 160);
#pragma unroll
        for (int r = 0; r < 4; r++) {
            float* rowp = series + (growbase + (gia + r)) * (size_t)LN;
            if (lbytes) bulk_store(rowp, zb_addr, lbytes);
            if (rlen > 0) bulk_store(rowp + jbase + 160, zb_addr, (unsigned)rlen * 4u);
        }
    }

    // ---- GEMM1: scores[4][5]; q broadcast via shfl, K via LDS.128 ----
    u64 acc[4][5];
#pragma unroll
    for (int r = 0; r < 4; r++)
#pragma unroll
        for (int s = 0; s < 5; s++) acc[r][s] = 0ull;

    const ulonglong2* kp[5];
#pragma unroll
    for (int s = 0; s < 5; s++) {
        const int row = min(off + lane + 32 * s, WROWS - 1);  // clamped lanes masked later
        kp[s] = (const ulonglong2*)(Ks + row * KSTR);
    }

#pragma unroll 4
    for (int it = 0; it < 16; it++) {
        u64 qa[4], qb[4];
#pragma unroll
        for (int r = 0; r < 4; r++) {
            qa[r] = __shfl_sync(0xffffffffu, q2[r], 2 * it);
            qb[r] = __shfl_sync(0xffffffffu, q2[r], 2 * it + 1);
        }
#pragma unroll
        for (int s = 0; s < 5; s++) {
            const ulonglong2 kk = kp[s][it];
            acc[0][s] = fma2(qa[0], kk.x, acc[0][s]);
            acc[0][s] = fma2(qb[0], kk.y, acc[0][s]);
            acc[1][s] = fma2(qa[1], kk.x, acc[1][s]);
            acc[1][s] = fma2(qb[1], kk.y, acc[1][s]);
            acc[2][s] = fma2(qa[2], kk.x, acc[2][s]);
            acc[2][s] = fma2(qb[2], kk.y, acc[2][s]);
            acc[3][s] = fma2(qa[3], kk.x, acc[3][s]);
            acc[3][s] = fma2(qb[3], kk.y, acc[3][s]);
        }
    }

    // ---- Ks dead block-wide -> Ps may overwrite ----
    __syncthreads();

    // ---- pass 1: raw p -> Ps (all 160 cols, zeros outside band), row sums ----
    float sum[4] = { 0.f, 0.f, 0.f, 0.f };
#pragma unroll
    for (int s = 0; s < 5; s++) {
        const int jj = lane + 32 * s;
        const int j  = jbase + jj;
#pragma unroll
        for (int r = 0; r < 4; r++) {
            const int gi = gia + r;
            const bool c = (jj <= spanw) && ((unsigned)(j - gi + 63) <= 126u);
            float p = 0.0f;
            if (c) {
                const float2 a = unpack2(acc[r][s]);
                p = ex2f(a.x + a.y);
                sum[r] += p;
            }
            Ps[(ga + r) * PSSTR + jj] = p;
        }
    }
#pragma unroll
    for (int o = 16; o > 0; o >>= 1)
#pragma unroll
        for (int r = 0; r < 4; r++)
            sum[r] += __shfl_xor_sync(0xffffffffu, sum[r], o);

    float rinv[4];
#pragma unroll
    for (int r = 0; r < 4; r++) rinv[r] = 1.0f / sum[r];

    // ---- series in-band: direct coalesced STG.32 of p*rinv over [jbase, jbase+160) ----
#pragma unroll
    for (int r = 0; r < 4; r++) {
        const float rv = rinv[r];
        float* rowp = series + (growbase + (gia + r)) * (size_t)LN;
        const float* prow = Ps + (ga + r) * PSSTR;
#pragma unroll
        for (int s = 0; s < 5; s++) {
            const int jj = lane + 32 * s;
            const int j  = jbase + jj;
            if (j < LN) __stcs(rowp + j, prow[jj] * rv);   // own-lane readback, no sync needed
        }
    }
    __syncwarp();   // Ps rows complete warp-wide for GEMM2 broadcasts

    // ---- GEMM2: V_out[4][64] over jj chunks; raw p, scale at epilogue ----
    u64 a0[4], a1[4];
#pragma unroll
    for (int r = 0; r < 4; r++) { a0[r] = 0ull; a1[r] = 0ull; }

    const int niter = (spanw >> 2) + 1;                 // <= 34
    const float* vt0 = VT + lane * VTSTR + off;
    const float* vt1 = VT + (lane + 32) * VTSTR + off;
#pragma unroll 2
    for (int it = 0; it < niter; it++) {
        const int jj = 4 * it;
        const ulonglong2 v0 = *(const ulonglong2*)(vt0 + jj);
        const ulonglong2 v1 = *(const ulonglong2*)(vt1 + jj);
#pragma unroll
        for (int r = 0; r < 4; r++) {
            const ulonglong2 pr = *(const ulonglong2*)(Ps + (ga + r) * PSSTR + jj);
            a0[r] = fma2(pr.x, v0.x, a0[r]);
            a0[r] = fma2(pr.y, v0.y, a0[r]);
            a1[r] = fma2(pr.x, v1.x, a1[r]);
            a1[r] = fma2(pr.y, v1.y, a1[r]);
        }
    }
#pragma unroll
    for (int r = 0; r < 4; r++) {
        const int gi = gia + r;
        const size_t o = (((size_t)b * LN + gi) * HN + h) * EN;
        const float2 x0 = unpack2(a0[r]);
        const float2 x1 = unpack2(a1[r]);
        out[o + lane]      = (x0.x + x0.y) * rinv[r];
        out[o + 32 + lane] = (x1.x + x1.y) * rinv[r];
    }

    // ---- drain async zero stores ----
    if (lane == 0) {
        asm volatile("cp.async.bulk.commit_group;" ::: "memory");
        asm volatile("cp.async.bulk.wait_group 0;" ::: "memory");
    }
}

extern "C" void kernel_launch(void* const* d_in, const int* in_sizes, int n_in,
                              void* d_out, int out_size) {
    const float* Q = (const float*)d_in[0];
    const float* K = (const float*)d_in[1];
    const float* V = (const float*)d_in[2];
    float* out = (float*)d_out;

    const int smem_bytes = (WROWS * KSTR + EN * VTSTR + ZB_FLOATS) * (int)sizeof(float);  // 110,592 B
    cudaFuncSetAttribute(anomaly_attn_kernel,
                         cudaFuncAttributeMaxDynamicSharedMemorySize, smem_bytes);

    dim3 grid(BN * HN * (LN / RT));   // 512 blocks
    dim3 block(512);
    anomaly_attn_kernel<<<grid, block, smem_bytes>>>(Q, K, V, out);
}

// round 10
// speedup vs baseline: 1.5164x; 1.5164x over previous
#include <cuda_runtime.h>
#include <math.h>

// AnomalyAttention: B=2, L=2048, H=8, E=64, band |i-j| <= 63.
// out = concat( V [B,L,H,E] f32 , series [B,H,L,L] f32 ).
// RT=64 tiles, 512 threads, 1 CTA/SM (RF-limited: 128 regs/thread).
// Series row = [0,jbase) zeros (bulk) | [jbase,jbase+160) direct STG | rest zeros (bulk).
// Q/K filled via cp.async (drain overlaps VT transpose gather).

#define BN 2
#define HN 8
#define LN 2048
#define EN 64
#define RT 64          // rows per block
#define WROWS 192      // K window rows
#define KSTR 68        // Q/K smem row stride (68%32=4 -> LDS.128 conflict-free)
#define VTSTR 196      // VT row stride (192 data + 4 pad; 196%32=4 -> conflict-free)
#define PSSTR 160      // Ps row stride (stride-1 lane access -> conflict-free)
#define ZB_FLOATS 2048 // zero source (max segment 1980 floats)
#define SCALE_L2E 0.18033688011112042f   // 0.125 * log2(e)

typedef unsigned long long u64;

__device__ __forceinline__ u64 fma2(u64 a, u64 b, u64 c) {
    u64 d;
    asm("fma.rn.f32x2 %0, %1, %2, %3;" : "=l"(d) : "l"(a), "l"(b), "l"(c));
    return d;
}
__device__ __forceinline__ float2 unpack2(u64 v) {
    float2 r;
    asm("mov.b64 {%0, %1}, %2;" : "=f"(r.x), "=f"(r.y) : "l"(v));
    return r;
}
__device__ __forceinline__ float ex2f(float x) {
    float y;
    asm("ex2.approx.ftz.f32 %0, %1;" : "=f"(y) : "f"(x));
    return y;
}
__device__ __forceinline__ unsigned smem_u32(const void* p) {
    return (unsigned)__cvta_generic_to_shared(p);
}
__device__ __forceinline__ void bulk_store(void* dst, unsigned src_smem, unsigned bytes) {
    asm volatile("cp.async.bulk.global.shared::cta.bulk_group [%0], [%1], %2;"
                 :: "l"(dst), "r"(src_smem), "r"(bytes) : "memory");
}
__device__ __forceinline__ void cp16(float* dst_smem, const float* src) {
    asm volatile("cp.async.cg.shared.global [%0], [%1], 16;"
                 :: "r"(smem_u32(dst_smem)), "l"(src) : "memory");
}

__global__ __launch_bounds__(512, 1)
void anomaly_attn_kernel(const float* __restrict__ Q,
                         const float* __restrict__ K,
                         const float* __restrict__ V,
                         float* __restrict__ out)
{
    extern __shared__ float sm[];
    float* Qs = sm;                        // RT    * KSTR = 4352
    float* Ks = Qs + RT * KSTR;            // WROWS * KSTR = 13056
    float* VT = Ks + WROWS * KSTR;         // EN * VTSTR   = 12544
    float* Ps = VT + EN * VTSTR;           // RT * PSSTR   = 10240 (raw p, window cols)
    float* Zb = Ps + RT * PSSTR;           // 2048 zeros

    const int bid = blockIdx.x;
    const int t   = bid & 31;
    const int h   = (bid >> 5) & 7;
    const int b   = bid >> 8;
    const int i0  = t * RT;
    const int wbase = min(max(i0 - 64, 0), LN - WROWS);

    const int tid  = threadIdx.x;
    const int lane = tid & 31;
    const int w    = tid >> 5;             // 16 warps x 4 rows
    const int ga   = 4 * w;
    const int gia  = i0 + ga;

    float* series = out + (size_t)BN * LN * HN * EN;
    const size_t growbase = (size_t)((b * HN + h) * LN);

    // ---- cp.async fill of Q and K (LDGSTS, deep MLP, no reg round-trip) ----
    {
        const int e4 = (tid & 15) * 4;
        const int r0 = tid >> 4;           // 0..31
#pragma unroll
        for (int r = r0; r < RT; r += 32)
            cp16(Qs + r * KSTR + e4, &Q[(((size_t)b * LN + (i0 + r)) * HN + h) * EN + e4]);
#pragma unroll
        for (int r = r0; r < WROWS; r += 32)
            cp16(Ks + r * KSTR + e4, &K[(((size_t)b * LN + (wbase + r)) * HN + h) * EN + e4]);
        asm volatile("cp.async.commit_group;" ::: "memory");
    }

    // ---- VT[e][col] transpose gather (overlaps cp.async drain) + Zb ----
    {
        const int e  = tid & 63;
        const int jg = (tid >> 6) * 4;     // 0..28
#pragma unroll
        for (int j4 = jg; j4 < WROWS; j4 += 32) {
            const float* vp = &V[(((size_t)b * LN + (wbase + j4)) * HN + h) * EN + e];
            float4 v;
            v.x = vp[0];
            v.y = vp[HN * EN];
            v.z = vp[2 * HN * EN];
            v.w = vp[3 * HN * EN];
            *(float4*)(VT + e * VTSTR + j4) = v;
        }
        *(float4*)(Zb + tid * 4) = make_float4(0.f, 0.f, 0.f, 0.f);   // 512*16B = 8KB
        if (tid < EN)   // VT pad cols 192..195
            *(float4*)(VT + tid * VTSTR + WROWS) = make_float4(0.f, 0.f, 0.f, 0.f);
    }
    asm volatile("cp.async.wait_group 0;" ::: "memory");
    __syncthreads();

    // ---- per-warp geometry: aligned 160-col store window ----
    const int jbase = max(0, gia - 63) & ~3;            // 16B aligned; >= wbase
    const int off   = jbase - wbase;                    // K/VT col of window col 0
    const int spanw = min(LN - 1, gia + 66) - jbase;    // <= 133

    // ---- issue zero-segment bulk stores (drain under all compute) ----
    if (lane == 0) {
        asm volatile("fence.proxy.async.shared::cta;" ::: "memory");
        const unsigned zb_addr = smem_u32(Zb);
        const unsigned lbytes = (unsigned)jbase * 4u;
        const int rlen = LN - (jbase + 160);
#pragma unroll
        for (int r = 0; r < 4; r++) {
            float* rowp = series + (growbase + (gia + r)) * (size_t)LN;
            if (lbytes) bulk_store(rowp, zb_addr, lbytes);
            if (rlen > 0) bulk_store(rowp + jbase + 160, zb_addr, (unsigned)rlen * 4u);
        }
    }

    // ---- GEMM1: scores[4][5], LDS.128 + f32x2 (R6 structure) ----
    u64 acc[4][5];
#pragma unroll
    for (int r = 0; r < 4; r++)
#pragma unroll
        for (int s = 0; s < 5; s++) acc[r][s] = 0ull;

    const ulonglong2* kp[5];
#pragma unroll
    for (int s = 0; s < 5; s++) {
        const int row = min(off + lane + 32 * s, WROWS - 1);  // clamped lanes masked later
        kp[s] = (const ulonglong2*)(Ks + row * KSTR);
    }
    const ulonglong2* qp0 = (const ulonglong2*)(Qs + (ga + 0) * KSTR);
    const ulonglong2* qp1 = (const ulonglong2*)(Qs + (ga + 1) * KSTR);
    const ulonglong2* qp2 = (const ulonglong2*)(Qs + (ga + 2) * KSTR);
    const ulonglong2* qp3 = (const ulonglong2*)(Qs + (ga + 3) * KSTR);

#pragma unroll 4
    for (int e4 = 0; e4 < EN / 4; e4++) {
        const ulonglong2 q0 = qp0[e4], q1 = qp1[e4], q2 = qp2[e4], q3 = qp3[e4];
#pragma unroll
        for (int s = 0; s < 5; s++) {
            const ulonglong2 kk = kp[s][e4];
            acc[0][s] = fma2(q0.x, kk.x, acc[0][s]);
            acc[0][s] = fma2(q0.y, kk.y, acc[0][s]);
            acc[1][s] = fma2(q1.x, kk.x, acc[1][s]);
            acc[1][s] = fma2(q1.y, kk.y, acc[1][s]);
            acc[2][s] = fma2(q2.x, kk.x, acc[2][s]);
            acc[2][s] = fma2(q2.y, kk.y, acc[2][s]);
            acc[3][s] = fma2(q3.x, kk.x, acc[3][s]);
            acc[3][s] = fma2(q3.y, kk.y, acc[3][s]);
        }
    }

    // ---- pass 1: raw p -> Ps (all 160 window cols; zeros where masked), row sums ----
    float sum[4] = { 0.f, 0.f, 0.f, 0.f };
#pragma unroll
    for (int s = 0; s < 5; s++) {
        const int jj = lane + 32 * s;
        const int j  = jbase + jj;
#pragma unroll
        for (int r = 0; r < 4; r++) {
            const int gi = gia + r;
            const bool c = (jj <= spanw) && ((unsigned)(j - gi + 63) <= 126u);
            float p = 0.0f;
            if (c) {
                const float2 a = unpack2(acc[r][s]);
                p = ex2f((a.x + a.y) * SCALE_L2E);
                sum[r] += p;
            }
            Ps[(ga + r) * PSSTR + jj] = p;
        }
    }
#pragma unroll
    for (int o = 16; o > 0; o >>= 1)
#pragma unroll
        for (int r = 0; r < 4; r++)
            sum[r] += __shfl_xor_sync(0xffffffffu, sum[r], o);

    float rinv[4];
#pragma unroll
    for (int r = 0; r < 4; r++) rinv[r] = 1.0f / sum[r];

    // ---- series in-band: direct coalesced STG.32 (own-lane Ps readback) ----
#pragma unroll
    for (int r = 0; r < 4; r++) {
        const float rv = rinv[r];
        float* rowp = series + (growbase + (gia + r)) * (size_t)LN;
        const float* prow = Ps + (ga + r) * PSSTR;
#pragma unroll
        for (int s = 0; s < 5; s++) {
            const int jj = lane + 32 * s;
            const int j  = jbase + jj;
            if (j < LN) __stcs(rowp + j, prow[jj] * rv);
        }
    }
    __syncwarp();   // all lanes' Ps stores visible for GEMM2 broadcast reads

    // ---- GEMM2: V_out[4][64] over window cols; raw p, normalize at epilogue ----
    u64 a0[4], a1[4];
#pragma unroll
    for (int r = 0; r < 4; r++) { a0[r] = 0ull; a1[r] = 0ull; }

    const int niter = (spanw >> 2) + 1;                 // <= 34
    const float* vt0 = VT + lane * VTSTR + off;
    const float* vt1 = VT + (lane + 32) * VTSTR + off;
#pragma unroll 4
    for (int it = 0; it < niter; it++) {
        const int jj = 4 * it;
        const ulonglong2 v0 = *(const ulonglong2*)(vt0 + jj);
        const ulonglong2 v1 = *(const ulonglong2*)(vt1 + jj);
#pragma unroll
        for (int r = 0; r < 4; r++) {
            const ulonglong2 pr = *(const ulonglong2*)(Ps + (ga + r) * PSSTR + jj);
            a0[r] = fma2(pr.x, v0.x, a0[r]);
            a0[r] = fma2(pr.y, v0.y, a0[r]);
            a1[r] = fma2(pr.x, v1.x, a1[r]);
            a1[r] = fma2(pr.y, v1.y, a1[r]);
        }
    }
#pragma unroll
    for (int r = 0; r < 4; r++) {
        const int gi = gia + r;
        const size_t o = (((size_t)b * LN + gi) * HN + h) * EN;
        const float2 x0 = unpack2(a0[r]);
        const float2 x1 = unpack2(a1[r]);
        out[o + lane]      = (x0.x + x0.y) * rinv[r];
        out[o + 32 + lane] = (x1.x + x1.y) * rinv[r];
    }

    // ---- drain async zero stores ----
    if (lane == 0) {
        asm volatile("cp.async.bulk.commit_group;" ::: "memory");
        asm volatile("cp.async.bulk.wait_group 0;" ::: "memory");
    }
}

extern "C" void kernel_launch(void* const* d_in, const int* in_sizes, int n_in,
                              void* d_out, int out_size) {
    const float* Q = (const float*)d_in[0];
    const float* K = (const float*)d_in[1];
    const float* V = (const float*)d_in[2];
    float* out = (float*)d_out;

    const int smem_bytes =
        (RT * KSTR + WROWS * KSTR + EN * VTSTR + RT * PSSTR + ZB_FLOATS) * (int)sizeof(float);
    cudaFuncSetAttribute(anomaly_attn_kernel,
                         cudaFuncAttributeMaxDynamicSharedMemorySize, smem_bytes);

    dim3 grid(BN * HN * (LN / RT));   // 512 blocks
    dim3 block(512);
    anomaly_attn_kernel<<<grid, block, smem_bytes>>>(Q, K, V, out);
}